// round 1
// baseline (speedup 1.0000x reference)
#include <cuda_runtime.h>
#include <math.h>

#define NU 100000
#define NI 50000
#define KN 100
#define DD 64
#define BB 8192

// Precomputed projected embeddings: pe_user = user_emb @ W1[:, :64]^T, etc.
__device__ float g_pe_user[NU * DD];
__device__ float g_pe_item[NI * DD];

// ---------------------------------------------------------------------------
// Precompute kernel: pe[n][o] = sum_d emb[n][d] * w1[o][w1_off + d]
// 16 rows per block, 256 threads (o = tid&63, row-group = tid>>6).
// ---------------------------------------------------------------------------
__global__ __launch_bounds__(256) void pe_kernel(
    const float* __restrict__ emb,
    const float* __restrict__ w1,
    int w1_off, int which, int nrows)
{
    __shared__ float w1t[64 * 65];   // [d][o], stride 65 kills bank conflicts
    __shared__ float ebuf[16][64];

    float* __restrict__ pe = which ? g_pe_item : g_pe_user;

    int tid = threadIdx.x;
    for (int t = tid; t < 4096; t += 256) {
        int o = t >> 6, d = t & 63;
        w1t[d * 65 + o] = w1[o * 128 + w1_off + d];
    }
    int n0 = blockIdx.x * 16;
    for (int t = tid; t < 1024; t += 256) {
        int r = t >> 6, d = t & 63;
        int n = n0 + r;
        ebuf[r][d] = (n < nrows) ? emb[n * 64 + d] : 0.f;
    }
    __syncthreads();

    int o = tid & 63, rg = tid >> 6;
    float a0 = 0.f, a1 = 0.f, a2 = 0.f, a3 = 0.f;
#pragma unroll
    for (int d = 0; d < 64; d++) {
        float w = w1t[d * 65 + o];
        a0 += ebuf[rg * 4 + 0][d] * w;
        a1 += ebuf[rg * 4 + 1][d] * w;
        a2 += ebuf[rg * 4 + 2][d] * w;
        a3 += ebuf[rg * 4 + 3][d] * w;
    }
    int n = n0 + rg * 4;
    if (n + 0 < nrows) pe[(n + 0) * 64 + o] = a0;
    if (n + 1 < nrows) pe[(n + 1) * 64 + o] = a1;
    if (n + 2 < nrows) pe[(n + 2) * 64 + o] = a2;
    if (n + 3 < nrows) pe[(n + 3) * 64 + o] = a3;
}

// ---------------------------------------------------------------------------
// Main kernel: one block per batch element.
// Smem layout (float offsets):
//   A    @ 0      : scr rows, [100][200]                     (20000)
//   Bm   @ 20000  : projected emb rows, [200][64]            (12800)
//   H    @ 32800  : h1 [100][64]; later h4 [100][34]         (6400)
//   H2   @ 0      : h2 [100][64]  (reuses A after GEMM1)
//   H3   @ 20000  : h3 [100][34]  (reuses Bm)
//   W2   @ 39200  : [64][68]                                 (4352)
//   W3   @ 43552  : [64][36]                                 (2304)
//   W4   @ 45856  : [32][36]                                 (1152)
//   W5   @ 47008  : [32]
//   RED  @ 47040  : [128]
//   nidx @ 47168  : 200 ints (user neighbors, item neighbors)
// Total: 47368 floats = 189472 bytes
// ---------------------------------------------------------------------------
#define SMEM_FLOATS 47368

__global__ __launch_bounds__(256) void cnn_main_kernel(
    const float* __restrict__ uscr, const float* __restrict__ iscr,
    const float* __restrict__ b1g,
    const float* __restrict__ w2g, const float* __restrict__ b2g,
    const float* __restrict__ w3g, const float* __restrict__ b3g,
    const float* __restrict__ w4g, const float* __restrict__ b4g,
    const float* __restrict__ w5g, const float* __restrict__ b5g,
    const int* __restrict__ uidxT, const int* __restrict__ iidxT,
    const int* __restrict__ uidxs, const int* __restrict__ iidxs,
    float* __restrict__ out)
{
    extern __shared__ float sm[];
    float* A   = sm;           // [100][200]
    float* Bm  = sm + 20000;   // [200][64]
    float* H   = sm + 32800;   // h1 [100][64] / h4 [100][34]
    float* H2  = sm;           // [100][64]
    float* H3  = sm + 20000;   // [100][34]
    float* W2  = sm + 39200;   // [64][68]
    float* W3  = sm + 43552;   // [64][36]
    float* W4  = sm + 45856;   // [32][36]
    float* W5  = sm + 47008;
    float* RED = sm + 47040;
    int*   nidx = (int*)(sm + 47168);

    const int tid = threadIdx.x;
    const int b = blockIdx.x;

    // Phase 0: neighbor indices + weights into smem
    if (tid < 200) {
        if (tid < 100) nidx[tid]       = uidxT[uidxs[b] * KN + tid];
        else           nidx[tid]       = iidxT[iidxs[b] * KN + (tid - 100)];
    }
    for (int t = tid; t < 4096; t += 256) { int o2 = t >> 6, o = t & 63; W2[o * 68 + o2] = w2g[t]; }
    for (int t = tid; t < 2048; t += 256) { int o3 = t >> 6, o = t & 63; W3[o * 36 + o3] = w3g[t]; }
    for (int t = tid; t < 1024; t += 256) { int o4 = t >> 5, o = t & 31; W4[o * 36 + o4] = w4g[t]; }
    if (tid < 32) W5[tid] = w5g[tid];
    __syncthreads();

    // Phase 1: gather projected embeddings (Bm) and scr rows (A), float4
    for (int t = tid; t < 200 * 16; t += 256) {
        int row = t >> 4, c = t & 15;
        int src = nidx[row];
        const float4* base = (row < 100) ? (const float4*)(g_pe_user + src * 64)
                                         : (const float4*)(g_pe_item + src * 64);
        ((float4*)Bm)[t] = base[c];
    }
    for (int t = tid; t < 100 * 50; t += 256) {
        int k = t / 50, c = t % 50;
        float4 v;
        if (c < 25) v = ((const float4*)(uscr + nidx[k] * KN))[c];
        else        v = ((const float4*)(iscr + nidx[100 + k] * KN))[c - 25];
        ((float4*)A)[k * 50 + c] = v;
    }
    __syncthreads();

    const int tx = tid & 15, ty = tid >> 4;
    int  krow[7];
    bool kval[7];
#pragma unroll
    for (int r = 0; r < 7; r++) {
        int k = ty + 16 * r;
        kval[r] = (k < 100);
        krow[r] = kval[r] ? k : 99;
    }

    // GEMM1: h1[k][o] = relu(b1[o] + sum_j A[k][j] * Bm[j][o]), j<200, o=tx*4..+3
    {
        float4 bias = *(const float4*)(b1g + tx * 4);
        float4 acc[7];
#pragma unroll
        for (int r = 0; r < 7; r++) acc[r] = bias;
#pragma unroll 2
        for (int j = 0; j < 200; j++) {
            float4 bv = *(const float4*)(Bm + j * 64 + tx * 4);
#pragma unroll
            for (int r = 0; r < 7; r++) {
                float a = A[krow[r] * 200 + j];
                acc[r].x += a * bv.x; acc[r].y += a * bv.y;
                acc[r].z += a * bv.z; acc[r].w += a * bv.w;
            }
        }
#pragma unroll
        for (int r = 0; r < 7; r++) if (kval[r]) {
            float4 v;
            v.x = fmaxf(acc[r].x, 0.f); v.y = fmaxf(acc[r].y, 0.f);
            v.z = fmaxf(acc[r].z, 0.f); v.w = fmaxf(acc[r].w, 0.f);
            *(float4*)(H + krow[r] * 64 + tx * 4) = v;
        }
    }
    __syncthreads();

    // Layer 2: h2[k][o2] = relu(b2 + sum_o h1[k][o] * W2[o][o2]), depth 64, out 64
    {
        float4 bias = *(const float4*)(b2g + tx * 4);
        float4 acc[7];
#pragma unroll
        for (int r = 0; r < 7; r++) acc[r] = bias;
#pragma unroll 2
        for (int o = 0; o < 64; o++) {
            float4 wv = *(const float4*)(W2 + o * 68 + tx * 4);
#pragma unroll
            for (int r = 0; r < 7; r++) {
                float a = H[krow[r] * 64 + o];
                acc[r].x += a * wv.x; acc[r].y += a * wv.y;
                acc[r].z += a * wv.z; acc[r].w += a * wv.w;
            }
        }
#pragma unroll
        for (int r = 0; r < 7; r++) if (kval[r]) {
            float4 v;
            v.x = fmaxf(acc[r].x, 0.f); v.y = fmaxf(acc[r].y, 0.f);
            v.z = fmaxf(acc[r].z, 0.f); v.w = fmaxf(acc[r].w, 0.f);
            *(float4*)(H2 + krow[r] * 64 + tx * 4) = v;
        }
    }
    __syncthreads();

    // Layer 3: h3[k][o3] = relu(b3 + sum_o h2[k][o] * W3[o][o3]), depth 64, out 32
    {
        float2 bias = *(const float2*)(b3g + tx * 2);
        float2 acc[7];
#pragma unroll
        for (int r = 0; r < 7; r++) acc[r] = bias;
#pragma unroll 2
        for (int o = 0; o < 64; o++) {
            float2 wv = *(const float2*)(W3 + o * 36 + tx * 2);
#pragma unroll
            for (int r = 0; r < 7; r++) {
                float a = H2[krow[r] * 64 + o];
                acc[r].x += a * wv.x; acc[r].y += a * wv.y;
            }
        }
#pragma unroll
        for (int r = 0; r < 7; r++) if (kval[r]) {
            float2 v;
            v.x = fmaxf(acc[r].x, 0.f); v.y = fmaxf(acc[r].y, 0.f);
            *(float2*)(H3 + krow[r] * 34 + tx * 2) = v;
        }
    }
    __syncthreads();

    // Layer 4: h4[k][o4] = relu(b4 + sum_o h3[k][o] * W4[o][o4]), depth 32, out 32
    {
        float2 bias = *(const float2*)(b4g + tx * 2);
        float2 acc[7];
#pragma unroll
        for (int r = 0; r < 7; r++) acc[r] = bias;
#pragma unroll 2
        for (int o = 0; o < 32; o++) {
            float2 wv = *(const float2*)(W4 + o * 36 + tx * 2);
#pragma unroll
            for (int r = 0; r < 7; r++) {
                float a = H3[krow[r] * 34 + o];
                acc[r].x += a * wv.x; acc[r].y += a * wv.y;
            }
        }
#pragma unroll
        for (int r = 0; r < 7; r++) if (kval[r]) {
            float2 v;
            v.x = fmaxf(acc[r].x, 0.f); v.y = fmaxf(acc[r].y, 0.f);
            *(float2*)(H + krow[r] * 34 + tx * 2) = v;   // h4 reuses H region
        }
    }
    __syncthreads();

    // Layer 5 + sigmoid + mean over k
    if (tid < 100) {
        float s = b5g[0];
#pragma unroll
        for (int o = 0; o < 32; o++) s += H[tid * 34 + o] * W5[o];
        RED[tid] = 1.f / (1.f + __expf(-s));
    }
    __syncthreads();
    if (tid < 32) {
        float v = RED[tid] + RED[tid + 32] + RED[tid + 64]
                + ((tid < 4) ? RED[tid + 96] : 0.f);
#pragma unroll
        for (int off = 16; off; off >>= 1)
            v += __shfl_down_sync(0xffffffffu, v, off);
        if (tid == 0) out[b] = v * (1.f / 100.f);
    }
}

// ---------------------------------------------------------------------------
extern "C" void kernel_launch(void* const* d_in, const int* in_sizes, int n_in,
                              void* d_out, int out_size)
{
    const float* user_emb = (const float*)d_in[0];
    const float* item_emb = (const float*)d_in[1];
    const float* user_scr = (const float*)d_in[2];
    const float* item_scr = (const float*)d_in[3];
    const float* w1 = (const float*)d_in[4];
    const float* b1 = (const float*)d_in[5];
    const float* w2 = (const float*)d_in[6];
    const float* b2 = (const float*)d_in[7];
    const float* w3 = (const float*)d_in[8];
    const float* b3 = (const float*)d_in[9];
    const float* w4 = (const float*)d_in[10];
    const float* b4 = (const float*)d_in[11];
    const float* w5 = (const float*)d_in[12];
    const float* b5 = (const float*)d_in[13];
    const int* user_idx_tensor = (const int*)d_in[14];
    const int* item_idx_tensor = (const int*)d_in[15];
    const int* user_idxs = (const int*)d_in[16];
    const int* item_idxs = (const int*)d_in[17];
    float* out = (float*)d_out;

    // Precompute projected embeddings (pushes MLP layer 1 through the pooling)
    pe_kernel<<<(NU + 15) / 16, 256>>>(user_emb, w1, 0, 0, NU);
    pe_kernel<<<(NI + 15) / 16, 256>>>(item_emb, w1, 64, 1, NI);

    const size_t smem_bytes = SMEM_FLOATS * sizeof(float);
    cudaFuncSetAttribute(cnn_main_kernel,
                         cudaFuncAttributeMaxDynamicSharedMemorySize,
                         (int)smem_bytes);
    cnn_main_kernel<<<BB, 256, smem_bytes>>>(
        user_scr, item_scr,
        b1, w2, b2, w3, b3, w4, b4, w5, b5,
        user_idx_tensor, item_idx_tensor, user_idxs, item_idxs,
        out);
}

// round 2
// speedup vs baseline: 1.5379x; 1.5379x over previous
#include <cuda_runtime.h>
#include <math.h>
#include <stdint.h>

#define NU 100000
#define NI 50000
#define KN 100
#define DD 64
#define BB 8192

// ---------------------------------------------------------------------------
// Smem layout (float offsets), 256 threads / CTA, one CTA per batch element.
//   A   [128][204]  @ 0       (scr rows, tf32-rounded; rows 100-127 garbage)
//   BT  [64][204]   @ 26112   (projected-emb transposed: BT[o][j])
//   H1  [128][68]   @ 39184
//   H2 = A region   (A dead after GEMM1)
//   H3 = BT region  (BT dead after GEMM1)
//   H4 = H1 region  (H1 dead after layer 2)
//   W2  [64][68]    @ 47888
//   W3  [32][68]    @ 52240
//   W4  [32][36]    @ 54416
//   W5  [32]        @ 55568
//   RED [128]       @ 55600
//   nidx[200] (int) @ 55728
// Total 55928 floats = 223712 bytes (< 227 KB limit)
// ---------------------------------------------------------------------------
#define OFF_A    0
#define OFF_BT   26112
#define OFF_H1   39184
#define OFF_H2   0
#define OFF_H3   26112
#define OFF_H4   39184
#define OFF_W2   47888
#define OFF_W3   52240
#define OFF_W4   54416
#define OFF_W5   55568
#define OFF_RED  55600
#define OFF_NIDX 55728
#define SMEM_FLOATS 55928

// Precomputed projected embeddings: pe_user = user_emb @ W1[:, :64]^T (tf32-rounded)
__device__ float g_pe_user[NU * DD];
__device__ float g_pe_item[NI * DD];

__device__ __forceinline__ float to_tf32(float x) {
    uint32_t u;
    asm("cvt.rna.tf32.f32 %0, %1;" : "=r"(u) : "f"(x));
    return __uint_as_float(u);
}
__device__ __forceinline__ float relu_tf32(float x) {
    return to_tf32(fmaxf(x, 0.f));
}

__device__ __forceinline__ void ldsm4(uint32_t (&r)[4], uint32_t a) {
    asm volatile("ldmatrix.sync.aligned.m8n8.x4.shared.b16 {%0,%1,%2,%3}, [%4];"
                 : "=r"(r[0]), "=r"(r[1]), "=r"(r[2]), "=r"(r[3]) : "r"(a));
}
__device__ __forceinline__ void ldsm2(uint32_t (&r)[2], uint32_t a) {
    asm volatile("ldmatrix.sync.aligned.m8n8.x2.shared.b16 {%0,%1}, [%2];"
                 : "=r"(r[0]), "=r"(r[1]) : "r"(a));
}
__device__ __forceinline__ void mma_tf32(float (&c)[4], const uint32_t (&a)[4],
                                         const uint32_t (&b)[2]) {
    asm volatile(
        "mma.sync.aligned.m16n8k8.row.col.f32.tf32.tf32.f32 "
        "{%0,%1,%2,%3}, {%4,%5,%6,%7}, {%8,%9}, {%0,%1,%2,%3};"
        : "+f"(c[0]), "+f"(c[1]), "+f"(c[2]), "+f"(c[3])
        : "r"(a[0]), "r"(a[1]), "r"(a[2]), "r"(a[3]), "r"(b[0]), "r"(b[1]));
}

// ---------------------------------------------------------------------------
// pe_kernel: pe[n][o] = tf32(sum_d emb[n][d] * w1[o][w1_off + d])
// ---------------------------------------------------------------------------
__global__ __launch_bounds__(256) void pe_kernel(
    const float* __restrict__ emb, const float* __restrict__ w1,
    int w1_off, int which, int nrows)
{
    __shared__ float w1t[64 * 65];
    __shared__ float ebuf[16][64];
    float* __restrict__ pe = which ? g_pe_item : g_pe_user;

    int tid = threadIdx.x;
    for (int t = tid; t < 4096; t += 256) {
        int o = t >> 6, d = t & 63;
        w1t[d * 65 + o] = w1[o * 128 + w1_off + d];
    }
    int n0 = blockIdx.x * 16;
    for (int t = tid; t < 1024; t += 256) {
        int r = t >> 6, d = t & 63;
        int n = n0 + r;
        ebuf[r][d] = (n < nrows) ? emb[n * 64 + d] : 0.f;
    }
    __syncthreads();

    int o = tid & 63, rg = tid >> 6;
    float a0 = 0.f, a1 = 0.f, a2 = 0.f, a3 = 0.f;
#pragma unroll
    for (int d = 0; d < 64; d++) {
        float w = w1t[d * 65 + o];
        a0 += ebuf[rg * 4 + 0][d] * w;
        a1 += ebuf[rg * 4 + 1][d] * w;
        a2 += ebuf[rg * 4 + 2][d] * w;
        a3 += ebuf[rg * 4 + 3][d] * w;
    }
    int n = n0 + rg * 4;
    if (n + 0 < nrows) pe[(n + 0) * 64 + o] = to_tf32(a0);
    if (n + 1 < nrows) pe[(n + 1) * 64 + o] = to_tf32(a1);
    if (n + 2 < nrows) pe[(n + 2) * 64 + o] = to_tf32(a2);
    if (n + 3 < nrows) pe[(n + 3) * 64 + o] = to_tf32(a3);
}

// ---------------------------------------------------------------------------
// One MLP GEMM layer on tensor cores.
// A: [128][K8*8] row-major, stride ASTR floats. B: [N][K] row-major ("BT"
// layout = mma col-major B), stride BSTR. C: [128][...] stride CSTR,
// epilogue = relu(acc + bias), tf32-rounded.
// Warp w: m-tiles {2*(w>>1), 2*(w>>1)+1}, n-tiles (w&1)*NT .. +NT-1.
// ---------------------------------------------------------------------------
template <int K8, int NT, int ASTR, int BSTR, int CSTR>
__device__ __forceinline__ void mma_layer(
    uint32_t sbase, int aOff, int bOff, int cOff,
    const float* __restrict__ biasg, float* __restrict__ sm)
{
    const int lane = threadIdx.x & 31;
    const int w = threadIdx.x >> 5;
    const int mw = w >> 1;   // 0..3
    const int nw = w & 1;    // 0..1

    uint32_t aAddr[2];
#pragma unroll
    for (int mt = 0; mt < 2; mt++)
        aAddr[mt] = sbase + (uint32_t)(aOff + (mw * 32 + mt * 16 + (lane & 15)) * ASTR) * 4u
                  + (uint32_t)((lane >> 4) << 4);
    uint32_t bAddr[NT];
#pragma unroll
    for (int nt = 0; nt < NT; nt++)
        bAddr[nt] = sbase + (uint32_t)(bOff + (nw * NT * 8 + nt * 8 + (lane & 7)) * BSTR) * 4u
                  + (uint32_t)(((lane >> 3) & 1) << 4);

    float acc[2][NT][4];
#pragma unroll
    for (int mt = 0; mt < 2; mt++)
#pragma unroll
        for (int nt = 0; nt < NT; nt++)
#pragma unroll
            for (int i = 0; i < 4; i++) acc[mt][nt][i] = 0.f;

    for (int ks = 0; ks < K8; ks++) {
        uint32_t b[NT][2];
#pragma unroll
        for (int nt = 0; nt < NT; nt++) ldsm2(b[nt], bAddr[nt] + ks * 32);
#pragma unroll
        for (int mt = 0; mt < 2; mt++) {
            uint32_t a[4];
            ldsm4(a, aAddr[mt] + ks * 32);
#pragma unroll
            for (int nt = 0; nt < NT; nt++) mma_tf32(acc[mt][nt], a, b[nt]);
        }
    }

    const int r = lane >> 2, cc = (lane & 3) * 2;
#pragma unroll
    for (int mt = 0; mt < 2; mt++) {
        int row = mw * 32 + mt * 16 + r;
#pragma unroll
        for (int nt = 0; nt < NT; nt++) {
            int col = nw * NT * 8 + nt * 8 + cc;
            float bx = biasg[col], by = biasg[col + 1];
            sm[cOff + row * CSTR + col]           = relu_tf32(acc[mt][nt][0] + bx);
            sm[cOff + row * CSTR + col + 1]       = relu_tf32(acc[mt][nt][1] + by);
            sm[cOff + (row + 8) * CSTR + col]     = relu_tf32(acc[mt][nt][2] + bx);
            sm[cOff + (row + 8) * CSTR + col + 1] = relu_tf32(acc[mt][nt][3] + by);
        }
    }
}

// ---------------------------------------------------------------------------
__global__ __launch_bounds__(256) void cnn_main_kernel(
    const float* __restrict__ uscr, const float* __restrict__ iscr,
    const float* __restrict__ b1g,
    const float* __restrict__ w2g, const float* __restrict__ b2g,
    const float* __restrict__ w3g, const float* __restrict__ b3g,
    const float* __restrict__ w4g, const float* __restrict__ b4g,
    const float* __restrict__ w5g, const float* __restrict__ b5g,
    const int* __restrict__ uidxT, const int* __restrict__ iidxT,
    const int* __restrict__ uidxs, const int* __restrict__ iidxs,
    float* __restrict__ out)
{
    extern __shared__ float sm[];
    int* nidx = (int*)(sm + OFF_NIDX);
    const int tid = threadIdx.x;
    const int b = blockIdx.x;
    uint32_t sbase = (uint32_t)__cvta_generic_to_shared(sm);

    // Phase 0: neighbor indices + weights (tf32-rounded) into smem
    if (tid < 200) {
        if (tid < 100) nidx[tid] = uidxT[uidxs[b] * KN + tid];
        else           nidx[tid] = iidxT[iidxs[b] * KN + (tid - 100)];
    }
    for (int t = tid; t < 4096; t += 256) sm[OFF_W2 + (t >> 6) * 68 + (t & 63)] = to_tf32(w2g[t]);
    for (int t = tid; t < 2048; t += 256) sm[OFF_W3 + (t >> 6) * 68 + (t & 63)] = to_tf32(w3g[t]);
    for (int t = tid; t < 1024; t += 256) sm[OFF_W4 + (t >> 5) * 36 + (t & 31)] = to_tf32(w4g[t]);
    if (tid < 32) sm[OFF_W5 + tid] = w5g[tid];
    __syncthreads();

    // Phase 1a: gather scr rows into A [128][204] (rows 0-99), tf32-rounded
    for (int t = tid; t < 100 * 50; t += 256) {
        int k = t / 50, c = t % 50;
        float4 v;
        if (c < 25) v = ((const float4*)(uscr + (size_t)nidx[k] * KN))[c];
        else        v = ((const float4*)(iscr + (size_t)nidx[100 + k] * KN))[c - 25];
        v.x = to_tf32(v.x); v.y = to_tf32(v.y); v.z = to_tf32(v.z); v.w = to_tf32(v.w);
        *(float4*)(sm + OFF_A + k * 204 + c * 4) = v;
    }
    // Phase 1b: gather projected embeddings transposed: BT[o][j] = pe[nidx[j]][o]
    // (pe values already tf32-rounded by pe_kernel)
    for (int t = tid; t < 200 * 16; t += 256) {
        int j = t % 200, db = t / 200;   // warp lanes -> consecutive j: conflict-free writes
        int src = nidx[j];
        const float4 v = (j < 100)
            ? *(const float4*)(g_pe_user + (size_t)src * 64 + db * 4)
            : *(const float4*)(g_pe_item + (size_t)src * 64 + db * 4);
        sm[OFF_BT + (db * 4 + 0) * 204 + j] = v.x;
        sm[OFF_BT + (db * 4 + 1) * 204 + j] = v.y;
        sm[OFF_BT + (db * 4 + 2) * 204 + j] = v.z;
        sm[OFF_BT + (db * 4 + 3) * 204 + j] = v.w;
    }
    __syncthreads();

    // GEMM1: H1[128][64] = relu(A[128][200] @ BT^T + b1)   (K=200 -> 25 k8 steps)
    mma_layer<25, 4, 204, 204, 68>(sbase, OFF_A, OFF_BT, OFF_H1, b1g, sm);
    __syncthreads();
    // Layer 2: H2 = relu(H1 @ W2^T + b2)    K=64, N=64
    mma_layer<8, 4, 68, 68, 68>(sbase, OFF_H1, OFF_W2, OFF_H2, b2g, sm);
    __syncthreads();
    // Layer 3: H3 = relu(H2 @ W3^T + b3)    K=64, N=32
    mma_layer<8, 2, 68, 68, 36>(sbase, OFF_H2, OFF_W3, OFF_H3, b3g, sm);
    __syncthreads();
    // Layer 4: H4 = relu(H3 @ W4^T + b4)    K=32, N=32
    mma_layer<4, 2, 36, 36, 36>(sbase, OFF_H3, OFF_W4, OFF_H4, b4g, sm);
    __syncthreads();

    // Layer 5 + sigmoid + mean over the 100 valid rows
    if (tid < 100) {
        float s = b5g[0];
#pragma unroll
        for (int o = 0; o < 32; o++) s += sm[OFF_H4 + tid * 36 + o] * sm[OFF_W5 + o];
        sm[OFF_RED + tid] = 1.f / (1.f + __expf(-s));
    }
    __syncthreads();
    if (tid < 32) {
        float v = sm[OFF_RED + tid] + sm[OFF_RED + tid + 32] + sm[OFF_RED + tid + 64]
                + ((tid < 4) ? sm[OFF_RED + tid + 96] : 0.f);
#pragma unroll
        for (int off = 16; off; off >>= 1)
            v += __shfl_down_sync(0xffffffffu, v, off);
        if (tid == 0) out[b] = v * (1.f / 100.f);
    }
}

// ---------------------------------------------------------------------------
extern "C" void kernel_launch(void* const* d_in, const int* in_sizes, int n_in,
                              void* d_out, int out_size)
{
    const float* user_emb = (const float*)d_in[0];
    const float* item_emb = (const float*)d_in[1];
    const float* user_scr = (const float*)d_in[2];
    const float* item_scr = (const float*)d_in[3];
    const float* w1 = (const float*)d_in[4];
    const float* b1 = (const float*)d_in[5];
    const float* w2 = (const float*)d_in[6];
    const float* b2 = (const float*)d_in[7];
    const float* w3 = (const float*)d_in[8];
    const float* b3 = (const float*)d_in[9];
    const float* w4 = (const float*)d_in[10];
    const float* b4 = (const float*)d_in[11];
    const float* w5 = (const float*)d_in[12];
    const float* b5 = (const float*)d_in[13];
    const int* user_idx_tensor = (const int*)d_in[14];
    const int* item_idx_tensor = (const int*)d_in[15];
    const int* user_idxs = (const int*)d_in[16];
    const int* item_idxs = (const int*)d_in[17];
    float* out = (float*)d_out;

    pe_kernel<<<(NU + 15) / 16, 256>>>(user_emb, w1, 0, 0, NU);
    pe_kernel<<<(NI + 15) / 16, 256>>>(item_emb, w1, 64, 1, NI);

    const size_t smem_bytes = SMEM_FLOATS * sizeof(float);
    cudaFuncSetAttribute(cnn_main_kernel,
                         cudaFuncAttributeMaxDynamicSharedMemorySize,
                         (int)smem_bytes);
    cnn_main_kernel<<<BB, 256, smem_bytes>>>(
        user_scr, item_scr,
        b1, w2, b2, w3, b3, w4, b4, w5, b5,
        user_idx_tensor, item_idx_tensor, user_idxs, item_idxs,
        out);
}

// round 4
// speedup vs baseline: 4.4847x; 2.9161x over previous
#include <cuda_runtime.h>
#include <cuda_fp16.h>
#include <math.h>
#include <stdint.h>

#define NU 100000
#define NI 50000
#define KN 100
#define BB 8192

// Precomputed projected embeddings (fp16): pe_user = user_emb @ W1[:, :64]^T
__device__ __half g_pe_user[NU * 64];
__device__ __half g_pe_item[NI * 64];

// ---------------------------------------------------------------------------
// Main-kernel SMEM layout (byte offsets), fp16 data:
//   A1 [112 r][216 k]  stride 432B   @ 0       (48384)   scr rows (k 200-215 zero)
//   B1 [208 k][72 n]   stride 144B   @ 48384   (29952)   pe gathered, k-major (rows 200-207 zero)
//   H1 [112][72]       stride 144B   @ 78336   (16128)   (H4 reuses)
//   H2 = A1 region, H3 = B1 region
//   W2 [64][72]        stride 144B   @ 94464   (9216)
//   W3 [32][72]        stride 144B   @ 103680  (4608)
//   W4 [32][40]        stride 80B    @ 108288  (2560)
//   MISC (floats)                    @ 110848  (2224)
// Total 113072 B -> 2 CTAs/SM (2x113072 = 226144 <= 228KB)
// ---------------------------------------------------------------------------
#define OFF_A1   0
#define OFF_B1   48384
#define OFF_H1   78336
#define OFF_H2   0
#define OFF_H3   48384
#define OFF_H4   78336
#define OFF_W2   94464
#define OFF_W3   103680
#define OFF_W4   108288
#define OFF_MISC 110848
#define SMEM_BYTES 113072
// MISC float indices
#define MISC_B1   0
#define MISC_B2   64
#define MISC_B3   128
#define MISC_B4   160
#define MISC_W5   192
#define MISC_B5   224
#define MISC_RED  228
#define MISC_NIDX 356

__device__ __forceinline__ void ldsm4(uint32_t (&r)[4], uint32_t a) {
    asm volatile("ldmatrix.sync.aligned.m8n8.x4.shared.b16 {%0,%1,%2,%3}, [%4];"
                 : "=r"(r[0]), "=r"(r[1]), "=r"(r[2]), "=r"(r[3]) : "r"(a));
}
__device__ __forceinline__ void ldsm2(uint32_t (&r)[2], uint32_t a) {
    asm volatile("ldmatrix.sync.aligned.m8n8.x2.shared.b16 {%0,%1}, [%2];"
                 : "=r"(r[0]), "=r"(r[1]) : "r"(a));
}
__device__ __forceinline__ void ldsm2t(uint32_t (&r)[2], uint32_t a) {
    asm volatile("ldmatrix.sync.aligned.m8n8.x2.trans.shared.b16 {%0,%1}, [%2];"
                 : "=r"(r[0]), "=r"(r[1]) : "r"(a));
}
__device__ __forceinline__ void mma_f16(float (&c)[4], const uint32_t (&a)[4],
                                        const uint32_t (&b)[2]) {
    asm volatile(
        "mma.sync.aligned.m16n8k16.row.col.f32.f16.f16.f32 "
        "{%0,%1,%2,%3}, {%4,%5,%6,%7}, {%8,%9}, {%0,%1,%2,%3};"
        : "+f"(c[0]), "+f"(c[1]), "+f"(c[2]), "+f"(c[3])
        : "r"(a[0]), "r"(a[1]), "r"(a[2]), "r"(a[3]), "r"(b[0]), "r"(b[1]));
}

__device__ __forceinline__ uint32_t h2_bits(float x, float y) {
    __half2 h = __floats2half2_rn(x, y);
    return *(uint32_t*)&h;
}
__device__ __forceinline__ void cvt_store4(char* dst, float4 v) {
    uint32_t lo = h2_bits(v.x, v.y), hi = h2_bits(v.z, v.w);
    uint2 u; u.x = lo; u.y = hi;
    *(uint2*)dst = u;
}

// ---------------------------------------------------------------------------
// pe_kernel (tensor core): pe[n][o] = fp16(sum_d emb[n][d] * w1[o][w1_off+d])
// 128 rows per block, 256 threads, 8 warps (one m16 tile each), N=64, K=64.
// ---------------------------------------------------------------------------
__global__ __launch_bounds__(256) void pe_kernel(
    const float* __restrict__ emb, const float* __restrict__ w1,
    int w1_off, int which, int nrows)
{
    __shared__ __half W1h[64 * 72];   // [o][k], stride 72 halves (144B)
    __shared__ __half E[128 * 72];    // [r][k], stride 72
    __half* __restrict__ pe = which ? g_pe_item : g_pe_user;

    const int tid = threadIdx.x;
    const int rows0 = blockIdx.x * 128;

    for (int t = tid; t < 64 * 16; t += 256) {
        int o = t >> 4, k4 = t & 15;
        float4 v = *(const float4*)(w1 + o * 128 + w1_off + k4 * 4);
        cvt_store4((char*)(W1h + o * 72 + k4 * 4), v);
    }
    for (int t = tid; t < 128 * 16; t += 256) {
        int r = t >> 4, k4 = t & 15;
        int n = rows0 + r;
        float4 v = (n < nrows) ? *(const float4*)(emb + (size_t)n * 64 + k4 * 4)
                               : make_float4(0.f, 0.f, 0.f, 0.f);
        cvt_store4((char*)(E + r * 72 + k4 * 4), v);
    }
    __syncthreads();

    const int lane = tid & 31, w = tid >> 5;
    uint32_t sE = (uint32_t)__cvta_generic_to_shared(E);
    uint32_t sW = (uint32_t)__cvta_generic_to_shared(W1h);
    uint32_t aAddr = sE + (uint32_t)(w * 16 + (lane & 15)) * 144u + (uint32_t)((lane >> 4) << 4);
    uint32_t bAddr0 = sW + (uint32_t)(lane & 7) * 144u + (uint32_t)(((lane >> 3) & 1) << 4);

    float acc[8][4];
#pragma unroll
    for (int nt = 0; nt < 8; nt++)
#pragma unroll
        for (int i = 0; i < 4; i++) acc[nt][i] = 0.f;

#pragma unroll
    for (int ks = 0; ks < 4; ks++) {
        uint32_t a[4];
        ldsm4(a, aAddr + ks * 32);
#pragma unroll
        for (int nt = 0; nt < 8; nt++) {
            uint32_t b[2];
            ldsm2(b, bAddr0 + (uint32_t)nt * 8u * 144u + ks * 32);
            mma_f16(acc[nt], a, b);
        }
    }

    int r0 = rows0 + w * 16 + (lane >> 2);
    int c0 = (lane & 3) * 2;
#pragma unroll
    for (int nt = 0; nt < 8; nt++) {
        int col = nt * 8 + c0;
        if (r0 < nrows) {
            __half2 h = __floats2half2_rn(acc[nt][0], acc[nt][1]);
            *(__half2*)(pe + (size_t)r0 * 64 + col) = h;
        }
        if (r0 + 8 < nrows) {
            __half2 h = __floats2half2_rn(acc[nt][2], acc[nt][3]);
            *(__half2*)(pe + (size_t)(r0 + 8) * 64 + col) = h;
        }
    }
}

// ---------------------------------------------------------------------------
// Generic fp16 layer: A [112][..] row-major, B = weights [N][K] n-major
// (non-trans ldsm), C = relu(A@B^T + bias) stored fp16.
// Warp w: mw=w>>1 (2 m-tiles each, mw==3 has 1), nw=w&1 (NT n-tiles).
// ---------------------------------------------------------------------------
template <int KS, int NT, int ASTR, int BSTR, int CSTR>
__device__ __forceinline__ void mma_layer_f16(
    uint32_t sbase, int aOff, int bOff, int cOff,
    const float* __restrict__ bias, char* __restrict__ smb)
{
    const int lane = threadIdx.x & 31;
    const int w = threadIdx.x >> 5;
    const int mw = w >> 1, nw = w & 1;
    const int mtn = (mw == 3) ? 1 : 2;

    uint32_t aAddr[2];
#pragma unroll
    for (int mt = 0; mt < 2; mt++)
        aAddr[mt] = sbase + (uint32_t)aOff
                  + (uint32_t)(mw * 32 + mt * 16 + (lane & 15)) * ASTR
                  + (uint32_t)((lane >> 4) << 4);
    uint32_t bAddr[NT];
#pragma unroll
    for (int nt = 0; nt < NT; nt++)
        bAddr[nt] = sbase + (uint32_t)bOff
                  + (uint32_t)(nw * NT * 8 + nt * 8 + (lane & 7)) * BSTR
                  + (uint32_t)(((lane >> 3) & 1) << 4);

    float acc[2][NT][4];
#pragma unroll
    for (int mt = 0; mt < 2; mt++)
#pragma unroll
        for (int nt = 0; nt < NT; nt++)
#pragma unroll
            for (int i = 0; i < 4; i++) acc[mt][nt][i] = 0.f;

#pragma unroll
    for (int ks = 0; ks < KS; ks++) {
        uint32_t b[NT][2];
#pragma unroll
        for (int nt = 0; nt < NT; nt++) ldsm2(b[nt], bAddr[nt] + ks * 32);
#pragma unroll
        for (int mt = 0; mt < 2; mt++) {
            if (mt < mtn) {
                uint32_t a[4];
                ldsm4(a, aAddr[mt] + ks * 32);
#pragma unroll
                for (int nt = 0; nt < NT; nt++) mma_f16(acc[mt][nt], a, b[nt]);
            }
        }
    }

    const int r = lane >> 2, cc = (lane & 3) * 2;
#pragma unroll
    for (int mt = 0; mt < 2; mt++) {
        if (mt < mtn) {
            int row = mw * 32 + mt * 16 + r;
#pragma unroll
            for (int nt = 0; nt < NT; nt++) {
                int col = nw * NT * 8 + nt * 8 + cc;
                float bx = bias[col], by = bias[col + 1];
                *(uint32_t*)(smb + cOff + row * CSTR + col * 2) =
                    h2_bits(fmaxf(acc[mt][nt][0] + bx, 0.f), fmaxf(acc[mt][nt][1] + by, 0.f));
                *(uint32_t*)(smb + cOff + (row + 8) * CSTR + col * 2) =
                    h2_bits(fmaxf(acc[mt][nt][2] + bx, 0.f), fmaxf(acc[mt][nt][3] + by, 0.f));
            }
        }
    }
}

// ---------------------------------------------------------------------------
__global__ __launch_bounds__(256, 2) void cnn_main_kernel(
    const float* __restrict__ uscr, const float* __restrict__ iscr,
    const float* __restrict__ b1g,
    const float* __restrict__ w2g, const float* __restrict__ b2g,
    const float* __restrict__ w3g, const float* __restrict__ b3g,
    const float* __restrict__ w4g, const float* __restrict__ b4g,
    const float* __restrict__ w5g, const float* __restrict__ b5g,
    const int* __restrict__ uidxT, const int* __restrict__ iidxT,
    const int* __restrict__ uidxs, const int* __restrict__ iidxs,
    float* __restrict__ out)
{
    extern __shared__ char smb[];
    float* misc = (float*)(smb + OFF_MISC);
    int* nidx = (int*)(misc + MISC_NIDX);
    uint32_t sbase = (uint32_t)__cvta_generic_to_shared(smb);
    const int tid = threadIdx.x;
    const int b = blockIdx.x;

    // Phase 0: neighbor indices, weights (fp16), biases (fp32)
    if (tid < 200) {
        nidx[tid] = (tid < 100) ? uidxT[(size_t)uidxs[b] * KN + tid]
                                : iidxT[(size_t)iidxs[b] * KN + (tid - 100)];
    }
    for (int t = tid; t < 64 * 16; t += 256) {
        int o = t >> 4, k4 = t & 15;
        cvt_store4(smb + OFF_W2 + o * 144 + k4 * 8, *(const float4*)(w2g + o * 64 + k4 * 4));
    }
    for (int t = tid; t < 32 * 16; t += 256) {
        int o = t >> 4, k4 = t & 15;
        cvt_store4(smb + OFF_W3 + o * 144 + k4 * 8, *(const float4*)(w3g + o * 64 + k4 * 4));
    }
    for (int t = tid; t < 32 * 8; t += 256) {
        int o = t >> 3, k4 = t & 7;
        cvt_store4(smb + OFF_W4 + o * 80 + k4 * 8, *(const float4*)(w4g + o * 32 + k4 * 4));
    }
    if (tid < 64) misc[MISC_B1 + tid] = b1g[tid];
    else if (tid < 128) misc[MISC_B2 + tid - 64] = b2g[tid - 64];
    else if (tid < 160) misc[MISC_B3 + tid - 128] = b3g[tid - 128];
    else if (tid < 192) misc[MISC_B4 + tid - 160] = b4g[tid - 160];
    else if (tid < 224) misc[MISC_W5 + tid - 192] = w5g[tid - 192];
    else if (tid == 224) misc[MISC_B5] = b5g[0];
    __syncthreads();

    // Phase 1: gathers (fp16) + zero pads
    // A1: scr rows [100][k<200], stride 432B
    for (int t = tid; t < 100 * 50; t += 256) {
        int r = t / 50, c4 = t % 50;
        float4 v;
        if (c4 < 25) v = ((const float4*)(uscr + (size_t)nidx[r] * KN))[c4];
        else         v = ((const float4*)(iscr + (size_t)nidx[100 + r] * KN))[c4 - 25];
        cvt_store4(smb + OFF_A1 + r * 432 + c4 * 8, v);
    }
    // A1 zero pad: all 112 rows, halves 200-215 (bytes 400-431)
    for (int t = tid; t < 224; t += 256) {
        int r = t >> 1;
        *(uint4*)(smb + OFF_A1 + r * 432 + 400 + (t & 1) * 16) = make_uint4(0, 0, 0, 0);
    }
    // B1: k-major gather: row j (=k) gets pe[nidx[j]][0..63] (128B = 8 uint4)
    for (int t = tid; t < 200 * 8; t += 256) {
        int j = t >> 3, c = t & 7;
        const uint4* src = (j < 100)
            ? (const uint4*)(g_pe_user + (size_t)nidx[j] * 64)
            : (const uint4*)(g_pe_item + (size_t)nidx[j] * 64);
        *(uint4*)(smb + OFF_B1 + j * 144 + c * 16) = src[c];
    }
    // B1 zero pad rows 200-207
    for (int t = tid; t < 64; t += 256) {
        int r = 200 + (t >> 3);
        *(uint4*)(smb + OFF_B1 + r * 144 + (t & 7) * 16) = make_uint4(0, 0, 0, 0);
    }
    __syncthreads();

    // GEMM1: H1 = relu(A1[112][200] @ B1 + b1), K=208 (13 k16 steps), N=64.
    // B1 is k-major [k][n] -> trans ldmatrix.
    {
        const int lane = tid & 31, w = tid >> 5;
        const int mw = w >> 1, nw = w & 1;
        const int mtn = (mw == 3) ? 1 : 2;

        uint32_t aAddr[2];
#pragma unroll
        for (int mt = 0; mt < 2; mt++)
            aAddr[mt] = sbase + OFF_A1
                      + (uint32_t)(mw * 32 + mt * 16 + (lane & 15)) * 432u
                      + (uint32_t)((lane >> 4) << 4);
        uint32_t bAddr[4];
#pragma unroll
        for (int nt = 0; nt < 4; nt++)
            bAddr[nt] = sbase + OFF_B1 + (uint32_t)(lane & 15) * 144u
                      + (uint32_t)((nw * 4 + nt) << 4);

        float acc[2][4][4];
#pragma unroll
        for (int mt = 0; mt < 2; mt++)
#pragma unroll
            for (int nt = 0; nt < 4; nt++)
#pragma unroll
                for (int i = 0; i < 4; i++) acc[mt][nt][i] = 0.f;

        for (int ks = 0; ks < 13; ks++) {
            uint32_t b[4][2];
#pragma unroll
            for (int nt = 0; nt < 4; nt++) ldsm2t(b[nt], bAddr[nt] + ks * 16 * 144);
#pragma unroll
            for (int mt = 0; mt < 2; mt++) {
                if (mt < mtn) {
                    uint32_t a[4];
                    ldsm4(a, aAddr[mt] + ks * 32);
#pragma unroll
                    for (int nt = 0; nt < 4; nt++) mma_f16(acc[mt][nt], a, b[nt]);
                }
            }
        }

        const int r = lane >> 2, cc = (lane & 3) * 2;
#pragma unroll
        for (int mt = 0; mt < 2; mt++) {
            if (mt < mtn) {
                int row = mw * 32 + mt * 16 + r;
#pragma unroll
                for (int nt = 0; nt < 4; nt++) {
                    int col = nw * 32 + nt * 8 + cc;
                    float bx = misc[MISC_B1 + col], by = misc[MISC_B1 + col + 1];
                    *(uint32_t*)(smb + OFF_H1 + row * 144 + col * 2) =
                        h2_bits(fmaxf(acc[mt][nt][0] + bx, 0.f), fmaxf(acc[mt][nt][1] + by, 0.f));
                    *(uint32_t*)(smb + OFF_H1 + (row + 8) * 144 + col * 2) =
                        h2_bits(fmaxf(acc[mt][nt][2] + bx, 0.f), fmaxf(acc[mt][nt][3] + by, 0.f));
                }
            }
        }
    }
    __syncthreads();

    // Layer 2: H2 = relu(H1 @ W2^T + b2)   K=64, N=64
    mma_layer_f16<4, 4, 144, 144, 144>(sbase, OFF_H1, OFF_W2, OFF_H2, misc + MISC_B2, smb);
    __syncthreads();
    // Layer 3: H3 = relu(H2 @ W3^T + b3)   K=64, N=32
    mma_layer_f16<4, 2, 144, 144, 80>(sbase, OFF_H2, OFF_W3, OFF_H3, misc + MISC_B3, smb);
    __syncthreads();
    // Layer 4: H4 = relu(H3 @ W4^T + b4)   K=32, N=32
    mma_layer_f16<2, 2, 80, 80, 80>(sbase, OFF_H3, OFF_W4, OFF_H4, misc + MISC_B4, smb);
    __syncthreads();

    // Layer 5 + sigmoid + mean over rows 0-99
    if (tid < 100) {
        float s = misc[MISC_B5];
#pragma unroll
        for (int o2 = 0; o2 < 16; o2++) {
            __half2 h = *(__half2*)(smb + OFF_H4 + tid * 80 + o2 * 4);
            float2 f = __half22float2(h);
            s += f.x * misc[MISC_W5 + o2 * 2] + f.y * misc[MISC_W5 + o2 * 2 + 1];
        }
        misc[MISC_RED + tid] = 1.f / (1.f + __expf(-s));
    }
    __syncthreads();
    if (tid < 32) {
        float v = misc[MISC_RED + tid] + misc[MISC_RED + tid + 32] + misc[MISC_RED + tid + 64]
                + ((tid < 4) ? misc[MISC_RED + tid + 96] : 0.f);
#pragma unroll
        for (int off = 16; off; off >>= 1)
            v += __shfl_down_sync(0xffffffffu, v, off);
        if (tid == 0) out[b] = v * (1.f / 100.f);
    }
}

// ---------------------------------------------------------------------------
extern "C" void kernel_launch(void* const* d_in, const int* in_sizes, int n_in,
                              void* d_out, int out_size)
{
    const float* user_emb = (const float*)d_in[0];
    const float* item_emb = (const float*)d_in[1];
    const float* user_scr = (const float*)d_in[2];
    const float* item_scr = (const float*)d_in[3];
    const float* w1 = (const float*)d_in[4];
    const float* b1 = (const float*)d_in[5];
    const float* w2 = (const float*)d_in[6];
    const float* b2 = (const float*)d_in[7];
    const float* w3 = (const float*)d_in[8];
    const float* b3 = (const float*)d_in[9];
    const float* w4 = (const float*)d_in[10];
    const float* b4 = (const float*)d_in[11];
    const float* w5 = (const float*)d_in[12];
    const float* b5 = (const float*)d_in[13];
    const int* user_idx_tensor = (const int*)d_in[14];
    const int* item_idx_tensor = (const int*)d_in[15];
    const int* user_idxs = (const int*)d_in[16];
    const int* item_idxs = (const int*)d_in[17];
    float* out = (float*)d_out;

    pe_kernel<<<(NU + 127) / 128, 256>>>(user_emb, w1, 0, 0, NU);
    pe_kernel<<<(NI + 127) / 128, 256>>>(item_emb, w1, 64, 1, NI);

    cudaFuncSetAttribute(cnn_main_kernel,
                         cudaFuncAttributeMaxDynamicSharedMemorySize, SMEM_BYTES);
    cnn_main_kernel<<<BB, 256, SMEM_BYTES>>>(
        user_scr, item_scr,
        b1, w2, b2, w3, b3, w4, b4, w5, b5,
        user_idx_tensor, item_idx_tensor, user_idxs, item_idxs,
        out);
}

// round 5
// speedup vs baseline: 9.1546x; 2.0413x over previous
#include <cuda_runtime.h>
#include <cuda_fp16.h>
#include <math.h>
#include <stdint.h>

#define NU 100000
#define NI 50000
#define KN 100
#define BB 8192

// Precomputed fp16 tables
__device__ __half g_pe_user[NU * 64];
__device__ __half g_pe_item[NI * 64];
__device__ __half g_uscr16[(size_t)NU * 112];   // scr rows padded to 112, cols 100-111 zero
__device__ __half g_iscr16[(size_t)NI * 112];
__device__ __half g_w2h[64 * 64];
__device__ __half g_w3h[32 * 64];
__device__ __half g_w4h[32 * 32];
__device__ __half g_b2h[64];
__device__ __half g_b3h[32];
__device__ __half g_b4h[32];

// ---------------------------------------------------------------------------
// Main-kernel SMEM (byte offsets):
//   A1 [112 r][232 k-halves] stride 464B  @ 0      (51968)  also H1(144)/H3(80)
//   B1 [224 k][72 n]        stride 144B  @ 51968  (32256)  also H2(144)/H4(80)
//   W2 [64][72h]  stride 144             @ 84224  (9216)
//   W3 [32][72h]  stride 144             @ 93440  (4608)
//   W4 [32][40h]  stride 80              @ 98048  (2560)
//   MISC (floats)                        @ 100608 (1344)
// Total 101952 B -> 2 CTAs/SM
// ---------------------------------------------------------------------------
#define OFF_A1   0
#define OFF_B1   51968
#define OFF_W2   84224
#define OFF_W3   93440
#define OFF_W4   98048
#define OFF_MISC 100608
#define SMEM_BYTES 101952
// MISC float indices
#define MISC_W5   0
#define MISC_B5   32
#define MISC_RED  33
#define MISC_NIDX 136

#define CP_ASYNC16(dst, src) \
    asm volatile("cp.async.cg.shared.global [%0], [%1], 16;" :: "r"(dst), "l"(src))
#define CP_COMMIT() asm volatile("cp.async.commit_group;" ::: "memory")
#define CP_WAIT0()  asm volatile("cp.async.wait_group 0;" ::: "memory")

__device__ __forceinline__ void ldsm4(uint32_t (&r)[4], uint32_t a) {
    asm volatile("ldmatrix.sync.aligned.m8n8.x4.shared.b16 {%0,%1,%2,%3}, [%4];"
                 : "=r"(r[0]), "=r"(r[1]), "=r"(r[2]), "=r"(r[3]) : "r"(a));
}
__device__ __forceinline__ void ldsm2(uint32_t (&r)[2], uint32_t a) {
    asm volatile("ldmatrix.sync.aligned.m8n8.x2.shared.b16 {%0,%1}, [%2];"
                 : "=r"(r[0]), "=r"(r[1]) : "r"(a));
}
__device__ __forceinline__ void ldsm2t(uint32_t (&r)[2], uint32_t a) {
    asm volatile("ldmatrix.sync.aligned.m8n8.x2.trans.shared.b16 {%0,%1}, [%2];"
                 : "=r"(r[0]), "=r"(r[1]) : "r"(a));
}
__device__ __forceinline__ void mma_f32acc(float (&c)[4], const uint32_t (&a)[4],
                                           const uint32_t (&b)[2]) {
    asm volatile(
        "mma.sync.aligned.m16n8k16.row.col.f32.f16.f16.f32 "
        "{%0,%1,%2,%3}, {%4,%5,%6,%7}, {%8,%9}, {%0,%1,%2,%3};"
        : "+f"(c[0]), "+f"(c[1]), "+f"(c[2]), "+f"(c[3])
        : "r"(a[0]), "r"(a[1]), "r"(a[2]), "r"(a[3]), "r"(b[0]), "r"(b[1]));
}
__device__ __forceinline__ void mma_f16acc(uint32_t (&c)[2], const uint32_t (&a)[4],
                                           const uint32_t (&b)[2]) {
    asm volatile(
        "mma.sync.aligned.m16n8k16.row.col.f16.f16.f16.f16 "
        "{%0,%1}, {%2,%3,%4,%5}, {%6,%7}, {%0,%1};"
        : "+r"(c[0]), "+r"(c[1])
        : "r"(a[0]), "r"(a[1]), "r"(a[2]), "r"(a[3]), "r"(b[0]), "r"(b[1]));
}

__device__ __forceinline__ uint32_t h2_bits(float x, float y) {
    __half2 h = __floats2half2_rn(x, y);
    return *(uint32_t*)&h;
}
__device__ __forceinline__ void cvt_store4(char* dst, float4 v) {
    uint32_t lo = h2_bits(v.x, v.y), hi = h2_bits(v.z, v.w);
    uint2 u; u.x = lo; u.y = hi;
    *(uint2*)dst = u;
}

// ---------------------------------------------------------------------------
// pe_kernel (tensor core): pe[n][o] = fp16(sum_d emb[n][d] * w1[o][w1_off+d])
// ---------------------------------------------------------------------------
__global__ __launch_bounds__(256) void pe_kernel(
    const float* __restrict__ emb, const float* __restrict__ w1,
    int w1_off, int which, int nrows)
{
    __shared__ __half W1h[64 * 72];
    __shared__ __half E[128 * 72];
    __half* __restrict__ pe = which ? g_pe_item : g_pe_user;

    const int tid = threadIdx.x;
    const int rows0 = blockIdx.x * 128;

    for (int t = tid; t < 64 * 16; t += 256) {
        int o = t >> 4, k4 = t & 15;
        float4 v = *(const float4*)(w1 + o * 128 + w1_off + k4 * 4);
        cvt_store4((char*)(W1h + o * 72 + k4 * 4), v);
    }
    for (int t = tid; t < 128 * 16; t += 256) {
        int r = t >> 4, k4 = t & 15;
        int n = rows0 + r;
        float4 v = (n < nrows) ? *(const float4*)(emb + (size_t)n * 64 + k4 * 4)
                               : make_float4(0.f, 0.f, 0.f, 0.f);
        cvt_store4((char*)(E + r * 72 + k4 * 4), v);
    }
    __syncthreads();

    const int lane = tid & 31, w = tid >> 5;
    uint32_t sE = (uint32_t)__cvta_generic_to_shared(E);
    uint32_t sW = (uint32_t)__cvta_generic_to_shared(W1h);
    uint32_t aAddr = sE + (uint32_t)(w * 16 + (lane & 15)) * 144u + (uint32_t)((lane >> 4) << 4);
    uint32_t bAddr0 = sW + (uint32_t)(lane & 7) * 144u + (uint32_t)(((lane >> 3) & 1) << 4);

    float acc[8][4];
#pragma unroll
    for (int nt = 0; nt < 8; nt++)
#pragma unroll
        for (int i = 0; i < 4; i++) acc[nt][i] = 0.f;

#pragma unroll
    for (int ks = 0; ks < 4; ks++) {
        uint32_t a[4];
        ldsm4(a, aAddr + ks * 32);
#pragma unroll
        for (int nt = 0; nt < 8; nt++) {
            uint32_t b[2];
            ldsm2(b, bAddr0 + (uint32_t)nt * 8u * 144u + ks * 32);
            mma_f32acc(acc[nt], a, b);
        }
    }

    int r0 = rows0 + w * 16 + (lane >> 2);
    int c0 = (lane & 3) * 2;
#pragma unroll
    for (int nt = 0; nt < 8; nt++) {
        int col = nt * 8 + c0;
        if (r0 < nrows) {
            __half2 h = __floats2half2_rn(acc[nt][0], acc[nt][1]);
            *(__half2*)(pe + (size_t)r0 * 64 + col) = h;
        }
        if (r0 + 8 < nrows) {
            __half2 h = __floats2half2_rn(acc[nt][2], acc[nt][3]);
            *(__half2*)(pe + (size_t)(r0 + 8) * 64 + col) = h;
        }
    }
}

// ---------------------------------------------------------------------------
// scr_cvt: fp32 scr [nrows][100] -> fp16 padded [nrows][112] (cols 100-111 = 0)
// One thread = one 8-half chunk (14 chunks/row).
// ---------------------------------------------------------------------------
__global__ __launch_bounds__(256) void scr_cvt_kernel(
    const float* __restrict__ src, int which, int nrows)
{
    __half* __restrict__ dst = which ? g_iscr16 : g_uscr16;
    int total = nrows * 14;
    for (int t = blockIdx.x * 256 + threadIdx.x; t < total; t += gridDim.x * 256) {
        int n = t / 14, cb = t % 14;
        uint32_t o[4] = {0, 0, 0, 0};
        if (cb < 12) {
            float4 a = *(const float4*)(src + (size_t)n * 100 + cb * 8);
            float4 bq = *(const float4*)(src + (size_t)n * 100 + cb * 8 + 4);
            o[0] = h2_bits(a.x, a.y);  o[1] = h2_bits(a.z, a.w);
            o[2] = h2_bits(bq.x, bq.y); o[3] = h2_bits(bq.z, bq.w);
        } else if (cb == 12) {
            float4 a = *(const float4*)(src + (size_t)n * 100 + 96);
            o[0] = h2_bits(a.x, a.y);  o[1] = h2_bits(a.z, a.w);
        }
        uint4 v; v.x = o[0]; v.y = o[1]; v.z = o[2]; v.w = o[3];
        *(uint4*)(dst + (size_t)n * 112 + cb * 8) = v;
    }
}

// ---------------------------------------------------------------------------
// wcvt: weights/biases of layers 2-4 -> fp16 device arrays
// ---------------------------------------------------------------------------
__global__ __launch_bounds__(256) void wcvt_kernel(
    const float* __restrict__ w2, const float* __restrict__ w3,
    const float* __restrict__ w4, const float* __restrict__ b2,
    const float* __restrict__ b3, const float* __restrict__ b4)
{
    int t = blockIdx.x * 256 + threadIdx.x;
    if (t < 4096) g_w2h[t] = __float2half_rn(w2[t]);
    else if (t < 6144) g_w3h[t - 4096] = __float2half_rn(w3[t - 4096]);
    else if (t < 7168) g_w4h[t - 6144] = __float2half_rn(w4[t - 6144]);
    else if (t < 7232) g_b2h[t - 7168] = __float2half_rn(b2[t - 7168]);
    else if (t < 7264) g_b3h[t - 7232] = __float2half_rn(b3[t - 7232]);
    else if (t < 7296) g_b4h[t - 7264] = __float2half_rn(b4[t - 7264]);
}

// ---------------------------------------------------------------------------
// f16-accum MLP layer: A row-major [112][K], B weights [N][K] n-major,
// C = relu(A@B^T + bias) fp16.
// ---------------------------------------------------------------------------
template <int KS, int NT, int ASTR, int BSTR, int CSTR>
__device__ __forceinline__ void layer_f16(
    uint32_t sbase, int aOff, int bOff, int cOff,
    const __half* __restrict__ bias, char* __restrict__ smb)
{
    const int lane = threadIdx.x & 31;
    const int w = threadIdx.x >> 5;
    const int mw = w >> 1, nw = w & 1;
    const int mtn = (mw == 3) ? 1 : 2;
    const int cc = (lane & 3) * 2;

    __half2 bias2[NT];
#pragma unroll
    for (int nt = 0; nt < NT; nt++)
        bias2[nt] = *(const __half2*)(bias + nw * NT * 8 + nt * 8 + cc);

    uint32_t aAddr[2];
#pragma unroll
    for (int mt = 0; mt < 2; mt++)
        aAddr[mt] = sbase + (uint32_t)aOff
                  + (uint32_t)(mw * 32 + mt * 16 + (lane & 15)) * ASTR
                  + (uint32_t)((lane >> 4) << 4);
    uint32_t bAddr[NT];
#pragma unroll
    for (int nt = 0; nt < NT; nt++)
        bAddr[nt] = sbase + (uint32_t)bOff
                  + (uint32_t)(nw * NT * 8 + nt * 8 + (lane & 7)) * BSTR
                  + (uint32_t)(((lane >> 3) & 1) << 4);

    uint32_t acc[2][NT][2];
#pragma unroll
    for (int mt = 0; mt < 2; mt++)
#pragma unroll
        for (int nt = 0; nt < NT; nt++) { acc[mt][nt][0] = 0u; acc[mt][nt][1] = 0u; }

#pragma unroll
    for (int ks = 0; ks < KS; ks++) {
        uint32_t b[NT][2];
#pragma unroll
        for (int nt = 0; nt < NT; nt++) ldsm2(b[nt], bAddr[nt] + ks * 32);
#pragma unroll
        for (int mt = 0; mt < 2; mt++) {
            if (mt < mtn) {
                uint32_t a[4];
                ldsm4(a, aAddr[mt] + ks * 32);
#pragma unroll
                for (int nt = 0; nt < NT; nt++) mma_f16acc(acc[mt][nt], a, b[nt]);
            }
        }
    }

    const int r = lane >> 2;
    const __half2 z = __floats2half2_rn(0.f, 0.f);
#pragma unroll
    for (int mt = 0; mt < 2; mt++) {
        if (mt < mtn) {
            int row = mw * 32 + mt * 16 + r;
#pragma unroll
            for (int nt = 0; nt < NT; nt++) {
                int col = nw * NT * 8 + nt * 8 + cc;
                __half2 v0 = __hmax2(__hadd2(*(__half2*)&acc[mt][nt][0], bias2[nt]), z);
                __half2 v1 = __hmax2(__hadd2(*(__half2*)&acc[mt][nt][1], bias2[nt]), z);
                *(uint32_t*)(smb + cOff + row * CSTR + col * 2) = *(uint32_t*)&v0;
                *(uint32_t*)(smb + cOff + (row + 8) * CSTR + col * 2) = *(uint32_t*)&v1;
            }
        }
    }
}

// ---------------------------------------------------------------------------
__global__ __launch_bounds__(256, 2) void cnn_main_kernel(
    const float* __restrict__ b1g,
    const float* __restrict__ w5g, const float* __restrict__ b5g,
    const int* __restrict__ uidxT, const int* __restrict__ iidxT,
    const int* __restrict__ uidxs, const int* __restrict__ iidxs,
    float* __restrict__ out)
{
    extern __shared__ char smb[];
    float* misc = (float*)(smb + OFF_MISC);
    int* nidx = (int*)(misc + MISC_NIDX);
    uint32_t sbase = (uint32_t)__cvta_generic_to_shared(smb);
    const int tid = threadIdx.x;
    const int b = blockIdx.x;

    // Phase 0: neighbor indices, w5/b5, zero B1 pad rows (k 100-111, 212-223)
    if (tid < 200) {
        nidx[tid] = (tid < 100) ? uidxT[(size_t)uidxs[b] * KN + tid]
                                : iidxT[(size_t)iidxs[b] * KN + (tid - 100)];
    } else if (tid < 232) {
        misc[MISC_W5 + tid - 200] = w5g[tid - 200];
    } else if (tid == 232) {
        misc[MISC_B5] = b5g[0];
    }
    if (tid < 192) {
        int rr = tid >> 3;
        int row = (rr < 12) ? 100 + rr : 200 + rr;
        *(uint4*)(smb + OFF_B1 + row * 144 + (tid & 7) * 16) = make_uint4(0, 0, 0, 0);
    }
    __syncthreads();

    // Phase 1: all gathers via cp.async (16B chunks)
    // A1: row r = [uscr16[nidx[r]] (224B incl pad) | iscr16[nidx[100+r]] (224B)]
    for (int t = tid; t < 2800; t += 256) {
        int r = t / 28, c = t % 28;
        const char* src = (c < 14)
            ? (const char*)(g_uscr16 + (size_t)nidx[r] * 112) + c * 16
            : (const char*)(g_iscr16 + (size_t)nidx[100 + r] * 112) + (c - 14) * 16;
        CP_ASYNC16(sbase + OFF_A1 + (uint32_t)(r * 464 + c * 16), src);
    }
    // B1: k-major pe rows; j<100 -> rows 0-99 (user), j>=100 -> rows 112-211 (item)
    for (int t = tid; t < 1600; t += 256) {
        int j = t >> 3, c = t & 7;
        const char* src = (j < 100)
            ? (const char*)(g_pe_user + (size_t)nidx[j] * 64) + c * 16
            : (const char*)(g_pe_item + (size_t)nidx[j] * 64) + c * 16;
        int dr = (j < 100) ? j : j + 12;
        CP_ASYNC16(sbase + OFF_B1 + (uint32_t)(dr * 144 + c * 16), src);
    }
    // Weights
    for (int t = tid; t < 512; t += 256) {
        int o = t >> 3, c = t & 7;
        CP_ASYNC16(sbase + OFF_W2 + (uint32_t)(o * 144 + c * 16),
                   (const char*)(g_w2h + o * 64 + c * 8));
    }
    if (tid < 256) {
        int o = tid >> 3, c = tid & 7;
        CP_ASYNC16(sbase + OFF_W3 + (uint32_t)(o * 144 + c * 16),
                   (const char*)(g_w3h + o * 64 + c * 8));
    }
    if (tid < 128) {
        int o = tid >> 2, c = tid & 3;
        CP_ASYNC16(sbase + OFF_W4 + (uint32_t)(o * 80 + c * 16),
                   (const char*)(g_w4h + o * 32 + c * 8));
    }
    CP_COMMIT();
    CP_WAIT0();
    __syncthreads();

    const int lane = tid & 31, w = tid >> 5;
    const int mw = w >> 1, nw = w & 1;
    const int mtn = (mw == 3) ? 1 : 2;
    const int cc = (lane & 3) * 2;

    // GEMM1 (fp32 accum): H1[112][64] = relu(A1[112][224] @ B1^T + b1), 14 k16 steps
    {
        float2 bfrag[4];
#pragma unroll
        for (int nt = 0; nt < 4; nt++)
            bfrag[nt] = *(const float2*)(b1g + nw * 32 + nt * 8 + cc);

        uint32_t aAddr[2];
#pragma unroll
        for (int mt = 0; mt < 2; mt++)
            aAddr[mt] = sbase + OFF_A1
                      + (uint32_t)(mw * 32 + mt * 16 + (lane & 15)) * 464u
                      + (uint32_t)((lane >> 4) << 4);
        uint32_t bAddr[4];
#pragma unroll
        for (int nt = 0; nt < 4; nt++)
            bAddr[nt] = sbase + OFF_B1 + (uint32_t)(lane & 15) * 144u
                      + (uint32_t)((nw * 4 + nt) << 4);

        float acc[2][4][4];
#pragma unroll
        for (int mt = 0; mt < 2; mt++)
#pragma unroll
            for (int nt = 0; nt < 4; nt++)
#pragma unroll
                for (int i = 0; i < 4; i++) acc[mt][nt][i] = 0.f;

#pragma unroll
        for (int ks = 0; ks < 14; ks++) {
            uint32_t bq[4][2];
#pragma unroll
            for (int nt = 0; nt < 4; nt++) ldsm2t(bq[nt], bAddr[nt] + ks * 2304);
#pragma unroll
            for (int mt = 0; mt < 2; mt++) {
                if (mt < mtn) {
                    uint32_t a[4];
                    ldsm4(a, aAddr[mt] + ks * 32);
#pragma unroll
                    for (int nt = 0; nt < 4; nt++) mma_f32acc(acc[mt][nt], a, bq[nt]);
                }
            }
        }
        __syncthreads();   // all A1/B1 reads done before H1 overwrites A1 region

        const int r = lane >> 2;
#pragma unroll
        for (int mt = 0; mt < 2; mt++) {
            if (mt < mtn) {
                int row = mw * 32 + mt * 16 + r;
#pragma unroll
                for (int nt = 0; nt < 4; nt++) {
                    int col = nw * 32 + nt * 8 + cc;
                    *(uint32_t*)(smb + OFF_A1 + row * 144 + col * 2) =
                        h2_bits(fmaxf(acc[mt][nt][0] + bfrag[nt].x, 0.f),
                                fmaxf(acc[mt][nt][1] + bfrag[nt].y, 0.f));
                    *(uint32_t*)(smb + OFF_A1 + (row + 8) * 144 + col * 2) =
                        h2_bits(fmaxf(acc[mt][nt][2] + bfrag[nt].x, 0.f),
                                fmaxf(acc[mt][nt][3] + bfrag[nt].y, 0.f));
                }
            }
        }
    }
    __syncthreads();

    // Layers 2-4, f16 accumulation, activations ping-pong A1<->B1 regions
    layer_f16<4, 4, 144, 144, 144>(sbase, OFF_A1, OFF_W2, OFF_B1, g_b2h, smb);
    __syncthreads();
    layer_f16<4, 2, 144, 144, 80>(sbase, OFF_B1, OFF_W3, OFF_A1, g_b3h, smb);
    __syncthreads();
    layer_f16<2, 2, 80, 80, 80>(sbase, OFF_A1, OFF_W4, OFF_B1, g_b4h, smb);
    __syncthreads();

    // Layer 5 + sigmoid + mean over rows 0-99 (H4 @ OFF_B1, stride 80)
    if (tid < 100) {
        float s = misc[MISC_B5];
#pragma unroll
        for (int o2 = 0; o2 < 16; o2++) {
            __half2 h = *(__half2*)(smb + OFF_B1 + tid * 80 + o2 * 4);
            float2 f = __half22float2(h);
            s += f.x * misc[MISC_W5 + o2 * 2] + f.y * misc[MISC_W5 + o2 * 2 + 1];
        }
        misc[MISC_RED + tid] = 1.f / (1.f + __expf(-s));
    }
    __syncthreads();
    if (tid < 32) {
        float v = misc[MISC_RED + tid] + misc[MISC_RED + tid + 32] + misc[MISC_RED + tid + 64]
                + ((tid < 4) ? misc[MISC_RED + tid + 96] : 0.f);
#pragma unroll
        for (int off = 16; off; off >>= 1)
            v += __shfl_down_sync(0xffffffffu, v, off);
        if (tid == 0) out[b] = v * (1.f / 100.f);
    }
}

// ---------------------------------------------------------------------------
extern "C" void kernel_launch(void* const* d_in, const int* in_sizes, int n_in,
                              void* d_out, int out_size)
{
    const float* user_emb = (const float*)d_in[0];
    const float* item_emb = (const float*)d_in[1];
    const float* user_scr = (const float*)d_in[2];
    const float* item_scr = (const float*)d_in[3];
    const float* w1 = (const float*)d_in[4];
    const float* b1 = (const float*)d_in[5];
    const float* w2 = (const float*)d_in[6];
    const float* b2 = (const float*)d_in[7];
    const float* w3 = (const float*)d_in[8];
    const float* b3 = (const float*)d_in[9];
    const float* w4 = (const float*)d_in[10];
    const float* b4 = (const float*)d_in[11];
    const float* w5 = (const float*)d_in[12];
    const float* b5 = (const float*)d_in[13];
    const int* user_idx_tensor = (const int*)d_in[14];
    const int* item_idx_tensor = (const int*)d_in[15];
    const int* user_idxs = (const int*)d_in[16];
    const int* item_idxs = (const int*)d_in[17];
    float* out = (float*)d_out;

    pe_kernel<<<(NU + 127) / 128, 256>>>(user_emb, w1, 0, 0, NU);
    pe_kernel<<<(NI + 127) / 128, 256>>>(item_emb, w1, 64, 1, NI);
    scr_cvt_kernel<<<(NU * 14 + 255) / 256, 256>>>(user_scr, 0, NU);
    scr_cvt_kernel<<<(NI * 14 + 255) / 256, 256>>>(item_scr, 1, NI);
    wcvt_kernel<<<29, 256>>>(w2, w3, w4, b2, b3, b4);

    cudaFuncSetAttribute(cnn_main_kernel,
                         cudaFuncAttributeMaxDynamicSharedMemorySize, SMEM_BYTES);
    cnn_main_kernel<<<BB, 256, SMEM_BYTES>>>(
        b1, w5, b5,
        user_idx_tensor, item_idx_tensor, user_idxs, item_idxs,
        out);
}